// round 11
// baseline (speedup 1.0000x reference)
#include <cuda_runtime.h>
#include <stdint.h>

#define BATCH 1024
#define KSEL  64
#define IFEAT 4096
#define OFEAT 4096

// Static device scratch (no runtime alloc).
__device__ float g_WT[(size_t)IFEAT * OFEAT];   // 64 MB, W transposed
__device__ float g_y[(size_t)BATCH * OFEAT];    // 16 MB

// ---------------------------------------------------------------------------
// Transpose W (O,I) -> WT (I,O). 64x64 tiles, float4 on both global sides.
// ---------------------------------------------------------------------------
__global__ __launch_bounds__(256) void transpose_kernel(const float* __restrict__ W)
{
    __shared__ float t[64][65];
    const int bc = blockIdx.x * 64;
    const int br = blockIdx.y * 64;
    const int tid = threadIdx.x;
    const int sub = tid & 15;
    const int grp = tid >> 4;
#pragma unroll
    for (int p = 0; p < 4; ++p) {
        int row = p * 16 + grp;
        int c4  = sub * 4;
        float4 v = *reinterpret_cast<const float4*>(
            W + (size_t)(br + row) * IFEAT + bc + c4);
        t[c4 + 0][row] = v.x;
        t[c4 + 1][row] = v.y;
        t[c4 + 2][row] = v.z;
        t[c4 + 3][row] = v.w;
    }
    __syncthreads();
#pragma unroll
    for (int p = 0; p < 4; ++p) {
        int c  = p * 16 + grp;
        int o4 = sub * 4;
        float4 v = make_float4(t[c][o4], t[c][o4 + 1], t[c][o4 + 2], t[c][o4 + 3]);
        *reinterpret_cast<float4*>(g_WT + (size_t)(bc + c) * OFEAT + br + o4) = v;
    }
}

// ---------------------------------------------------------------------------
// Batched sparse gemv (proven, ~55us): float4/thread, 1024 outs/block,
// exact sequential-k FMA chain, bias last (bit-exact vs reference).
// ---------------------------------------------------------------------------
__global__ __launch_bounds__(256) void gemv_kernel(const float* __restrict__ x,
                                                   const int*   __restrict__ idx,
                                                   const float* __restrict__ bias)
{
    __shared__ float sx[KSEL];
    __shared__ int   soff[KSEL];

    const int b = blockIdx.y;
    const int o = blockIdx.x * 1024 + threadIdx.x * 4;

    if (threadIdx.x < KSEL) {
        sx[threadIdx.x]   = x[b * KSEL + threadIdx.x];
        soff[threadIdx.x] = idx[b * KSEL + threadIdx.x] * OFEAT;
    }
    __syncthreads();

    float4 a = make_float4(0.f, 0.f, 0.f, 0.f);
#pragma unroll 8
    for (int k = 0; k < KSEL; ++k) {
        const float xv = sx[k];
        const float4 w = *reinterpret_cast<const float4*>(g_WT + soff[k] + o);
        a.x = fmaf(xv, w.x, a.x);
        a.y = fmaf(xv, w.y, a.y);
        a.z = fmaf(xv, w.z, a.z);
        a.w = fmaf(xv, w.w, a.w);
    }
    const float4 bb = *reinterpret_cast<const float4*>(bias + o);
    *reinterpret_cast<float4*>(g_y + (size_t)b * OFEAT + o) =
        make_float4(a.x + bb.x, a.y + bb.y, a.z + bb.z, a.w + bb.w);
}

// ---------------------------------------------------------------------------
// Exact top-64 v3: reg-resident values, 2 radix passes, warp-aggregated
// compaction, hybrid register/smem bitonic (identical comparator network:
// desc = ((i & k2) == 0); j2 < 32 stages via shuffles, j2 >= 32 via smem).
// ---------------------------------------------------------------------------
__device__ __forceinline__ unsigned f2u(float f) {
    unsigned u = __float_as_uint(f);
    return (u & 0x80000000u) ? ~u : (u | 0x80000000u);
}
__device__ __forceinline__ float u2f(unsigned u) {
    unsigned b = (u & 0x80000000u) ? (u ^ 0x80000000u) : ~u;
    return __uint_as_float(b);
}
__device__ __forceinline__ unsigned long long kmax_(unsigned long long a, unsigned long long b) { return a > b ? a : b; }
__device__ __forceinline__ unsigned long long kmin_(unsigned long long a, unsigned long long b) { return a < b ? a : b; }

__global__ __launch_bounds__(512) void topk_kernel(float* __restrict__ out, int out_size)
{
    __shared__ unsigned hist[256];
    __shared__ unsigned long long cand[256];
    __shared__ unsigned sh_bin;
    __shared__ int sh_need;
    __shared__ int ncand;

    const int b = blockIdx.x;
    const int tid = threadIdx.x;
    const int warp = tid >> 5, lane = tid & 31;

    // 8 values per thread in registers.
    unsigned u[8];
    {
        const float4* yp = reinterpret_cast<const float4*>(g_y + (size_t)b * OFEAT) + tid * 2;
        float4 v0 = yp[0], v1 = yp[1];
        u[0] = f2u(v0.x); u[1] = f2u(v0.y); u[2] = f2u(v0.z); u[3] = f2u(v0.w);
        u[4] = f2u(v1.x); u[5] = f2u(v1.y); u[6] = f2u(v1.z); u[7] = f2u(v1.w);
    }

    // --- 2-pass radix select of the 16-bit prefix containing rank-64 ---
    unsigned prefix = 0;
    int need = KSEL;
#pragma unroll
    for (int pass = 0; pass < 2; ++pass) {
        if (tid < 256) hist[tid] = 0;
        __syncthreads();
        if (pass == 0) {
#pragma unroll
            for (int j = 0; j < 8; ++j)
                atomicAdd(&hist[u[j] >> 24], 1u);
        } else {
#pragma unroll
            for (int j = 0; j < 8; ++j)
                if ((u[j] >> 24) == prefix)
                    atomicAdd(&hist[(u[j] >> 16) & 255], 1u);
        }
        __syncthreads();
        if (warp == 0) {
            int s = 0;
#pragma unroll
            for (int j = 0; j < 8; ++j) s += (int)hist[lane * 8 + j];
            int S = s;
#pragma unroll
            for (int off = 1; off < 32; off <<= 1) {
                int v = __shfl_down_sync(0xFFFFFFFFu, S, off);
                if (lane + off < 32) S += v;
            }
            int Snext = __shfl_down_sync(0xFFFFFFFFu, S, 1);
            if (lane == 31) Snext = 0;
            unsigned m = __ballot_sync(0xFFFFFFFFu, S >= need);
            int lc = 31 - __clz(m);
            if (lane == lc) {
                int cum = Snext;
                for (int bin = lc * 8 + 7; bin >= lc * 8; --bin) {
                    cum += (int)hist[bin];
                    if (cum >= need) {
                        sh_bin  = (unsigned)bin;
                        sh_need = need - (cum - (int)hist[bin]);
                        break;
                    }
                }
            }
        }
        __syncthreads();
        prefix = (prefix << 8) | sh_bin;
        need   = sh_need;
        __syncthreads();
    }
    const unsigned P16 = prefix;

    // --- Warp-aggregated candidate compaction (order fixed by the sort) ---
    if (tid == 0) ncand = 0;
    if (tid < 256) cand[tid] = 0ull;
    __syncthreads();
    {
        bool pr[8];
        int myc = 0;
#pragma unroll
        for (int j = 0; j < 8; ++j) {
            pr[j] = ((u[j] >> 16) >= P16);
            myc += pr[j] ? 1 : 0;
        }
        int inc = myc;
#pragma unroll
        for (int d = 1; d < 32; d <<= 1) {
            int v = __shfl_up_sync(0xFFFFFFFFu, inc, d);
            if (lane >= d) inc += v;
        }
        int excl = inc - myc;
        int wtot = __shfl_sync(0xFFFFFFFFu, inc, 31);
        int wb = 0;
        if (lane == 31 && wtot > 0) wb = atomicAdd(&ncand, wtot);
        wb = __shfl_sync(0xFFFFFFFFu, wb, 31);
        int pos = wb + excl;
#pragma unroll
        for (int j = 0; j < 8; ++j) {
            if (pr[j] && pos < 256) {
                int o = tid * 8 + j;
                cand[pos++] = ((unsigned long long)u[j] << 32) | (unsigned)(4095 - o);
            }
        }
    }
    __syncthreads();

    // --- Hybrid bitonic sort of 256 keys (desc), comparator-identical ---
    unsigned long long key = 0ull;
    if (tid < 256) key = cand[tid];

    // k2 = 2..32: fully in-warp (i = tid, partner in same warp).
    if (tid < 256) {
#pragma unroll
        for (int k2 = 2; k2 <= 32; k2 <<= 1) {
#pragma unroll
            for (int j2 = k2 >> 1; j2 > 0; j2 >>= 1) {
                unsigned long long p = __shfl_xor_sync(0xFFFFFFFFu, key, j2);
                bool low  = ((lane & j2) == 0);
                bool desc = ((tid & k2) == 0);
                key = (desc == low) ? kmax_(key, p) : kmin_(key, p);
            }
        }
    }

    // k2 = 64, 128, 256: j2 >= 32 via smem, j2 <= 16 via shuffles.
#pragma unroll
    for (int k2 = 64; k2 <= 256; k2 <<= 1) {
        for (int j2 = k2 >> 1; j2 >= 32; j2 >>= 1) {
            if (tid < 256) cand[tid] = key;
            __syncthreads();
            if (tid < 256) {
                unsigned long long p = cand[tid ^ j2];
                bool low  = ((tid & j2) == 0);
                bool desc = ((tid & k2) == 0);
                key = (desc == low) ? kmax_(key, p) : kmin_(key, p);
            }
            __syncthreads();
        }
        if (tid < 256) {
            bool desc = ((tid & k2) == 0);
#pragma unroll
            for (int j2 = 16; j2 > 0; j2 >>= 1) {
                unsigned long long p = __shfl_xor_sync(0xFFFFFFFFu, key, j2);
                bool low = ((lane & j2) == 0);
                key = (desc == low) ? kmax_(key, p) : kmin_(key, p);
            }
        }
    }

    if (tid < KSEL) {
        unsigned uu = (unsigned)(key >> 32);
        int o = 4095 - (int)(key & 0xFFFFFFFFull);
        int half = out_size >> 1;
        out[(size_t)b * KSEL + tid]        = u2f(uu);
        out[(size_t)half + b * KSEL + tid] = (float)o;
    }
}

// ---------------------------------------------------------------------------
extern "C" void kernel_launch(void* const* d_in, const int* in_sizes, int n_in,
                              void* d_out, int out_size)
{
    const float* input  = nullptr;
    const float* weight = nullptr;
    const float* bias   = nullptr;
    const int*   idx    = nullptr;
    for (int i = 0; i < n_in; ++i) {
        if (in_sizes[i] == OFEAT * IFEAT)      weight = (const float*)d_in[i];
        else if (in_sizes[i] == OFEAT)         bias   = (const float*)d_in[i];
        else if (in_sizes[i] == BATCH * KSEL) {
            if (!input) input = (const float*)d_in[i];
            else        idx   = (const int*)d_in[i];
        }
    }

    transpose_kernel<<<dim3(IFEAT / 64, OFEAT / 64), 256>>>(weight);
    gemv_kernel<<<dim3(OFEAT / 1024, BATCH), 256>>>(input, idx, bias);
    topk_kernel<<<BATCH, 512>>>((float*)d_out, out_size);
}

// round 12
// speedup vs baseline: 1.2124x; 1.2124x over previous
#include <cuda_runtime.h>
#include <stdint.h>

#define BATCH 1024
#define KSEL  64
#define IFEAT 4096
#define OFEAT 4096

// Static device scratch (no runtime alloc).
__device__ float g_WT[(size_t)IFEAT * OFEAT];                 // 64 MB, W transposed
__device__ unsigned long long g_cand[(size_t)BATCH * 128];    // per-half top-64 keys

// ---------------------------------------------------------------------------
// Transpose W (O,I) -> WT (I,O). 64x64 tiles, float4 on both global sides.
// ---------------------------------------------------------------------------
__global__ __launch_bounds__(256) void transpose_kernel(const float* __restrict__ W)
{
    __shared__ float t[64][65];
    const int bc = blockIdx.x * 64;
    const int br = blockIdx.y * 64;
    const int tid = threadIdx.x;
    const int sub = tid & 15;
    const int grp = tid >> 4;
#pragma unroll
    for (int p = 0; p < 4; ++p) {
        int row = p * 16 + grp;
        int c4  = sub * 4;
        float4 v = *reinterpret_cast<const float4*>(
            W + (size_t)(br + row) * IFEAT + bc + c4);
        t[c4 + 0][row] = v.x;
        t[c4 + 1][row] = v.y;
        t[c4 + 2][row] = v.z;
        t[c4 + 3][row] = v.w;
    }
    __syncthreads();
#pragma unroll
    for (int p = 0; p < 4; ++p) {
        int c  = p * 16 + grp;
        int o4 = sub * 4;
        float4 v = make_float4(t[c][o4], t[c][o4 + 1], t[c][o4 + 2], t[c][o4 + 3]);
        *reinterpret_cast<float4*>(g_WT + (size_t)(bc + c) * OFEAT + br + o4) = v;
    }
}

// ---------------------------------------------------------------------------
// Monotone key helpers.
// ---------------------------------------------------------------------------
__device__ __forceinline__ unsigned f2u(float f) {
    unsigned u = __float_as_uint(f);
    return (u & 0x80000000u) ? ~u : (u | 0x80000000u);
}
__device__ __forceinline__ float u2f(unsigned u) {
    unsigned b = (u & 0x80000000u) ? (u ^ 0x80000000u) : ~u;
    return __uint_as_float(b);
}

// ---------------------------------------------------------------------------
// Fused gemv + per-half exact top-64.
// Block (half, b): 512 threads, outputs [half*2048, half*2048+2048).
// gemv: exact sequential-k FMA chain per output, bias last (bit-exact).
// select: 2-pass radix (need=64 within 2048), compact >=P16, bitonic-256,
// emit 64 composite keys (value desc, index asc via 4095-o) to g_cand.
// ---------------------------------------------------------------------------
__global__ __launch_bounds__(512) void gemv_topk_kernel(const float* __restrict__ x,
                                                        const int*   __restrict__ idx,
                                                        const float* __restrict__ bias)
{
    __shared__ float sx[KSEL];
    __shared__ int   soff[KSEL];
    __shared__ unsigned hist[256];
    __shared__ unsigned long long cand[256];
    __shared__ unsigned sh_bin;
    __shared__ int sh_need;
    __shared__ int ncand;

    const int half = blockIdx.x;          // 0 or 1
    const int b    = blockIdx.y;
    const int tid  = threadIdx.x;
    const int warp = tid >> 5, lane = tid & 31;
    const int o    = half * 2048 + tid * 4;

    if (tid < KSEL) {
        sx[tid]   = x[b * KSEL + tid];
        soff[tid] = idx[b * KSEL + tid] * OFEAT;
    }
    __syncthreads();

    // --- gemv: 4 outputs per thread, exact chain ---
    float4 a = make_float4(0.f, 0.f, 0.f, 0.f);
#pragma unroll 8
    for (int k = 0; k < KSEL; ++k) {
        const float xv = sx[k];
        const float4 w = *reinterpret_cast<const float4*>(g_WT + soff[k] + o);
        a.x = fmaf(xv, w.x, a.x);
        a.y = fmaf(xv, w.y, a.y);
        a.z = fmaf(xv, w.z, a.z);
        a.w = fmaf(xv, w.w, a.w);
    }
    const float4 bb = *reinterpret_cast<const float4*>(bias + o);
    unsigned u[4];
    u[0] = f2u(a.x + bb.x);
    u[1] = f2u(a.y + bb.y);
    u[2] = f2u(a.z + bb.z);
    u[3] = f2u(a.w + bb.w);

    // --- 2-pass radix select of 16-bit prefix containing this half's rank-64 ---
    unsigned prefix = 0;
    int need = KSEL;
#pragma unroll
    for (int pass = 0; pass < 2; ++pass) {
        if (tid < 256) hist[tid] = 0;
        __syncthreads();
        if (pass == 0) {
#pragma unroll
            for (int j = 0; j < 4; ++j)
                atomicAdd(&hist[u[j] >> 24], 1u);
        } else {
#pragma unroll
            for (int j = 0; j < 4; ++j)
                if ((u[j] >> 24) == prefix)
                    atomicAdd(&hist[(u[j] >> 16) & 255], 1u);
        }
        __syncthreads();
        if (warp == 0) {
            int s = 0;
#pragma unroll
            for (int j = 0; j < 8; ++j) s += (int)hist[lane * 8 + j];
            int S = s;
#pragma unroll
            for (int off = 1; off < 32; off <<= 1) {
                int v = __shfl_down_sync(0xFFFFFFFFu, S, off);
                if (lane + off < 32) S += v;
            }
            int Snext = __shfl_down_sync(0xFFFFFFFFu, S, 1);
            if (lane == 31) Snext = 0;
            unsigned m = __ballot_sync(0xFFFFFFFFu, S >= need);
            int lc = 31 - __clz(m);
            if (lane == lc) {
                int cum = Snext;
                for (int bin = lc * 8 + 7; bin >= lc * 8; --bin) {
                    cum += (int)hist[bin];
                    if (cum >= need) {
                        sh_bin  = (unsigned)bin;
                        sh_need = need - (cum - (int)hist[bin]);
                        break;
                    }
                }
            }
        }
        __syncthreads();
        prefix = (prefix << 8) | sh_bin;
        need   = sh_need;
        __syncthreads();
    }
    const unsigned P16 = prefix;

    // --- Collect candidates (all u with top-16 bits >= P16; <= 256) ---
    if (tid == 0) ncand = 0;
    if (tid < 256) cand[tid] = 0ull;
    __syncthreads();
#pragma unroll
    for (int j = 0; j < 4; ++j) {
        if ((u[j] >> 16) >= P16) {
            int p = atomicAdd(&ncand, 1);
            if (p < 256) {
                int oo = o + j;
                cand[p] = ((unsigned long long)u[j] << 32) | (unsigned)(4095 - oo);
            }
        }
    }
    __syncthreads();

    // --- Bitonic sort 256 (value desc, index asc), proven comparator net ---
    for (int k2 = 2; k2 <= 256; k2 <<= 1) {
        for (int j2 = k2 >> 1; j2 > 0; j2 >>= 1) {
            if (tid < 256) {
                int i = tid, ixj = tid ^ j2;
                if (ixj > i) {
                    bool desc = ((i & k2) == 0);
                    unsigned long long aa = cand[i], bb2 = cand[ixj];
                    if (desc ? (aa < bb2) : (aa > bb2)) { cand[i] = bb2; cand[ixj] = aa; }
                }
            }
            __syncthreads();
        }
    }

    // --- Emit this half's exact top-64 keys ---
    if (tid < KSEL)
        g_cand[((size_t)b * 2 + half) * KSEL + tid] = cand[tid];
}

// ---------------------------------------------------------------------------
// Merge: per sample, top-64 of the union of the two half top-64 lists.
// 128 threads, bitonic-128 on unique composite keys -> deterministic, exact.
// ---------------------------------------------------------------------------
__global__ __launch_bounds__(128) void merge_kernel(float* __restrict__ out, int out_size)
{
    __shared__ unsigned long long cand[128];
    const int b = blockIdx.x;
    const int tid = threadIdx.x;

    cand[tid] = g_cand[(size_t)b * 128 + tid];
    __syncthreads();

    for (int k2 = 2; k2 <= 128; k2 <<= 1) {
        for (int j2 = k2 >> 1; j2 > 0; j2 >>= 1) {
            int i = tid, ixj = tid ^ j2;
            if (ixj > i) {
                bool desc = ((i & k2) == 0);
                unsigned long long aa = cand[i], bb = cand[ixj];
                if (desc ? (aa < bb) : (aa > bb)) { cand[i] = bb; cand[ixj] = aa; }
            }
            __syncthreads();
        }
    }

    if (tid < KSEL) {
        unsigned long long key = cand[tid];
        unsigned uu = (unsigned)(key >> 32);
        int o = 4095 - (int)(key & 0xFFFFFFFFull);
        int half = out_size >> 1;
        out[(size_t)b * KSEL + tid]        = u2f(uu);
        out[(size_t)half + b * KSEL + tid] = (float)o;
    }
}

// ---------------------------------------------------------------------------
extern "C" void kernel_launch(void* const* d_in, const int* in_sizes, int n_in,
                              void* d_out, int out_size)
{
    const float* input  = nullptr;
    const float* weight = nullptr;
    const float* bias   = nullptr;
    const int*   idx    = nullptr;
    for (int i = 0; i < n_in; ++i) {
        if (in_sizes[i] == OFEAT * IFEAT)      weight = (const float*)d_in[i];
        else if (in_sizes[i] == OFEAT)         bias   = (const float*)d_in[i];
        else if (in_sizes[i] == BATCH * KSEL) {
            if (!input) input = (const float*)d_in[i];
            else        idx   = (const int*)d_in[i];
        }
    }

    transpose_kernel<<<dim3(IFEAT / 64, OFEAT / 64), 256>>>(weight);
    gemv_topk_kernel<<<dim3(2, BATCH), 512>>>(input, idx, bias);
    merge_kernel<<<BATCH, 128>>>((float*)d_out, out_size);
}

// round 13
// speedup vs baseline: 1.3312x; 1.0980x over previous
#include <cuda_runtime.h>
#include <stdint.h>

#define BATCH 1024
#define KSEL  64
#define IFEAT 4096
#define OFEAT 4096

// Static device scratch (no runtime alloc).
__device__ float g_WT[(size_t)IFEAT * OFEAT];   // 64 MB, W transposed

// ---------------------------------------------------------------------------
// Transpose W (O,I) -> WT (I,O). 64x64 tiles, float4 on both global sides.
// ---------------------------------------------------------------------------
__global__ __launch_bounds__(256) void transpose_kernel(const float* __restrict__ W)
{
    __shared__ float t[64][65];
    const int bc = blockIdx.x * 64;
    const int br = blockIdx.y * 64;
    const int tid = threadIdx.x;
    const int sub = tid & 15;
    const int grp = tid >> 4;
#pragma unroll
    for (int p = 0; p < 4; ++p) {
        int row = p * 16 + grp;
        int c4  = sub * 4;
        float4 v = *reinterpret_cast<const float4*>(
            W + (size_t)(br + row) * IFEAT + bc + c4);
        t[c4 + 0][row] = v.x;
        t[c4 + 1][row] = v.y;
        t[c4 + 2][row] = v.z;
        t[c4 + 3][row] = v.w;
    }
    __syncthreads();
#pragma unroll
    for (int p = 0; p < 4; ++p) {
        int c  = p * 16 + grp;
        int o4 = sub * 4;
        float4 v = make_float4(t[c][o4], t[c][o4 + 1], t[c][o4 + 2], t[c][o4 + 3]);
        *reinterpret_cast<float4*>(g_WT + (size_t)(bc + c) * OFEAT + br + o4) = v;
    }
}

// ---------------------------------------------------------------------------
// Monotone key helpers.
// ---------------------------------------------------------------------------
__device__ __forceinline__ unsigned f2u(float f) {
    unsigned u = __float_as_uint(f);
    return (u & 0x80000000u) ? ~u : (u | 0x80000000u);
}
__device__ __forceinline__ float u2f(unsigned u) {
    unsigned b = (u & 0x80000000u) ? (u ^ 0x80000000u) : ~u;
    return __uint_as_float(b);
}
__device__ __forceinline__ unsigned long long kmax_(unsigned long long a, unsigned long long b) { return a > b ? a : b; }
__device__ __forceinline__ unsigned long long kmin_(unsigned long long a, unsigned long long b) { return a < b ? a : b; }

// ---------------------------------------------------------------------------
// Fused per-sample gemv + exact top-64, one block per sample.
// 1024 threads; thread t owns outputs [4t, 4t+4): exact sequential-k FMA
// chain per output, bias last (bit-exact vs reference einsum + bias).
// Then: 2-pass radix select (rank-64 over all 4096), warp-aggregated
// compaction of u>=P16 (<=256 candidates), hybrid register/smem bitonic-256
// on composite keys (value desc, index asc) == jax.lax.top_k order. Output
// written directly (values first half, indices-as-float second half).
// ---------------------------------------------------------------------------
__global__ __launch_bounds__(1024) void gemv_topk_kernel(const float* __restrict__ x,
                                                         const int*   __restrict__ idx,
                                                         const float* __restrict__ bias,
                                                         float* __restrict__ out,
                                                         int out_size)
{
    __shared__ float sx[KSEL];
    __shared__ int   soff[KSEL];
    __shared__ unsigned hist[256];
    __shared__ unsigned long long cand[256];
    __shared__ unsigned sh_bin;
    __shared__ int sh_need;
    __shared__ int ncand;

    const int b   = blockIdx.x;
    const int tid = threadIdx.x;
    const int warp = tid >> 5, lane = tid & 31;
    const int o   = tid * 4;

    if (tid < KSEL) {
        sx[tid]   = x[b * KSEL + tid];
        soff[tid] = idx[b * KSEL + tid] * OFEAT;
    }
    __syncthreads();

    // --- gemv: 4 outputs/thread, exact chain ---
    float4 a = make_float4(0.f, 0.f, 0.f, 0.f);
#pragma unroll 8
    for (int k = 0; k < KSEL; ++k) {
        const float xv = sx[k];
        const float4 w = *reinterpret_cast<const float4*>(g_WT + soff[k] + o);
        a.x = fmaf(xv, w.x, a.x);
        a.y = fmaf(xv, w.y, a.y);
        a.z = fmaf(xv, w.z, a.z);
        a.w = fmaf(xv, w.w, a.w);
    }
    const float4 bb = *reinterpret_cast<const float4*>(bias + o);
    unsigned u[4];
    u[0] = f2u(a.x + bb.x);
    u[1] = f2u(a.y + bb.y);
    u[2] = f2u(a.z + bb.z);
    u[3] = f2u(a.w + bb.w);

    // --- 2-pass radix select of the 16-bit prefix containing rank-64 ---
    unsigned prefix = 0;
    int need = KSEL;
#pragma unroll
    for (int pass = 0; pass < 2; ++pass) {
        if (tid < 256) hist[tid] = 0;
        __syncthreads();
        if (pass == 0) {
#pragma unroll
            for (int j = 0; j < 4; ++j)
                atomicAdd(&hist[u[j] >> 24], 1u);
        } else {
#pragma unroll
            for (int j = 0; j < 4; ++j)
                if ((u[j] >> 24) == prefix)
                    atomicAdd(&hist[(u[j] >> 16) & 255], 1u);
        }
        __syncthreads();
        if (warp == 0) {
            int s = 0;
#pragma unroll
            for (int j = 0; j < 8; ++j) s += (int)hist[lane * 8 + j];
            int S = s;
#pragma unroll
            for (int off = 1; off < 32; off <<= 1) {
                int v = __shfl_down_sync(0xFFFFFFFFu, S, off);
                if (lane + off < 32) S += v;
            }
            int Snext = __shfl_down_sync(0xFFFFFFFFu, S, 1);
            if (lane == 31) Snext = 0;
            unsigned m = __ballot_sync(0xFFFFFFFFu, S >= need);
            int lc = 31 - __clz(m);
            if (lane == lc) {
                int cum = Snext;
                for (int bin = lc * 8 + 7; bin >= lc * 8; --bin) {
                    cum += (int)hist[bin];
                    if (cum >= need) {
                        sh_bin  = (unsigned)bin;
                        sh_need = need - (cum - (int)hist[bin]);
                        break;
                    }
                }
            }
        }
        __syncthreads();
        prefix = (prefix << 8) | sh_bin;
        need   = sh_need;
        __syncthreads();
    }
    const unsigned P16 = prefix;

    // --- Warp-aggregated candidate compaction (order fixed by full sort) ---
    if (tid == 0) ncand = 0;
    if (tid < 256) cand[tid] = 0ull;
    __syncthreads();
    {
        bool pr[4];
        int myc = 0;
#pragma unroll
        for (int j = 0; j < 4; ++j) {
            pr[j] = ((u[j] >> 16) >= P16);
            myc += pr[j] ? 1 : 0;
        }
        int inc = myc;
#pragma unroll
        for (int d = 1; d < 32; d <<= 1) {
            int v = __shfl_up_sync(0xFFFFFFFFu, inc, d);
            if (lane >= d) inc += v;
        }
        int excl = inc - myc;
        int wtot = __shfl_sync(0xFFFFFFFFu, inc, 31);
        int wb = 0;
        if (lane == 31 && wtot > 0) wb = atomicAdd(&ncand, wtot);
        wb = __shfl_sync(0xFFFFFFFFu, wb, 31);
        int pos = wb + excl;
#pragma unroll
        for (int j = 0; j < 4; ++j) {
            if (pr[j] && pos < 256) {
                int oo = o + j;
                cand[pos++] = ((unsigned long long)u[j] << 32) | (unsigned)(4095 - oo);
            }
        }
    }
    __syncthreads();

    // --- Hybrid bitonic sort of 256 keys (desc), comparator-identical ---
    unsigned long long key = 0ull;
    if (tid < 256) key = cand[tid];

    if (tid < 256) {
#pragma unroll
        for (int k2 = 2; k2 <= 32; k2 <<= 1) {
#pragma unroll
            for (int j2 = k2 >> 1; j2 > 0; j2 >>= 1) {
                unsigned long long p = __shfl_xor_sync(0xFFFFFFFFu, key, j2);
                bool low  = ((lane & j2) == 0);
                bool desc = ((tid & k2) == 0);
                key = (desc == low) ? kmax_(key, p) : kmin_(key, p);
            }
        }
    }
#pragma unroll
    for (int k2 = 64; k2 <= 256; k2 <<= 1) {
        for (int j2 = k2 >> 1; j2 >= 32; j2 >>= 1) {
            if (tid < 256) cand[tid] = key;
            __syncthreads();
            if (tid < 256) {
                unsigned long long p = cand[tid ^ j2];
                bool low  = ((tid & j2) == 0);
                bool desc = ((tid & k2) == 0);
                key = (desc == low) ? kmax_(key, p) : kmin_(key, p);
            }
            __syncthreads();
        }
        if (tid < 256) {
            bool desc = ((tid & k2) == 0);
#pragma unroll
            for (int j2 = 16; j2 > 0; j2 >>= 1) {
                unsigned long long p = __shfl_xor_sync(0xFFFFFFFFu, key, j2);
                bool low = ((lane & j2) == 0);
                key = (desc == low) ? kmax_(key, p) : kmin_(key, p);
            }
        }
    }

    if (tid < KSEL) {
        unsigned uu = (unsigned)(key >> 32);
        int oo = 4095 - (int)(key & 0xFFFFFFFFull);
        int half = out_size >> 1;
        out[(size_t)b * KSEL + tid]        = u2f(uu);
        out[(size_t)half + b * KSEL + tid] = (float)oo;
    }
}

// ---------------------------------------------------------------------------
extern "C" void kernel_launch(void* const* d_in, const int* in_sizes, int n_in,
                              void* d_out, int out_size)
{
    const float* input  = nullptr;
    const float* weight = nullptr;
    const float* bias   = nullptr;
    const int*   idx    = nullptr;
    for (int i = 0; i < n_in; ++i) {
        if (in_sizes[i] == OFEAT * IFEAT)      weight = (const float*)d_in[i];
        else if (in_sizes[i] == OFEAT)         bias   = (const float*)d_in[i];
        else if (in_sizes[i] == BATCH * KSEL) {
            if (!input) input = (const float*)d_in[i];
            else        idx   = (const int*)d_in[i];
        }
    }

    transpose_kernel<<<dim3(IFEAT / 64, OFEAT / 64), 256>>>(weight);
    gemv_topk_kernel<<<BATCH, 1024>>>(input, idx, bias, (float*)d_out, out_size);
}